// round 11
// baseline (speedup 1.0000x reference)
#include <cuda_runtime.h>
#include <cstdint>

#define DD 128
#define NMAX 50176
#define EMAX 800256
#define NCHUNK 4

// ---------------- scratch (__device__ globals; no allocation) ----------------
__device__ float g_h[2][(size_t)NMAX * DD];     // double-buffered post-linear h
__device__ float g_h2[(size_t)NMAX * DD];       // agg output (gemm input)
__device__ float g_slb[2][NMAX], g_srb[2][NMAX];
__device__ int   g_deg[NMAX];
__device__ int   g_off[NMAX + 1];
__device__ int   g_pos[NMAX];
__device__ int   g_col[EMAX];

// ---------------- CSR build ----------------
__global__ void k_zero(int N) {
    int i = blockIdx.x * blockDim.x + threadIdx.x;
    if (i < N) g_deg[i] = 0;
}
__global__ void k_count(const int* __restrict__ src, int E) {
    int e = blockIdx.x * blockDim.x + threadIdx.x;
    if (e < E) atomicAdd(&g_deg[src[e]], 1);
}
__global__ __launch_bounds__(1024) void k_scan(int N, int E) {
    __shared__ int sh[1024];
    int tid = threadIdx.x;
    int per = (N + 1023) >> 10;
    int s = tid * per;
    int e = s + per; if (e > N) e = N;
    int sum = 0;
    for (int i = s; i < e; i++) sum += g_deg[i];
    sh[tid] = sum;
    __syncthreads();
    for (int o = 1; o < 1024; o <<= 1) {
        int t = (tid >= o) ? sh[tid - o] : 0;
        __syncthreads();
        sh[tid] += t;
        __syncthreads();
    }
    int run = sh[tid] - sum;
    for (int i = s; i < e; i++) { g_off[i] = run; g_pos[i] = run; run += g_deg[i]; }
    if (tid == 1023) g_off[N] = E;
}
__global__ void k_scatter(const int* __restrict__ src, const int* __restrict__ dst, int E) {
    int e = blockIdx.x * blockDim.x + threadIdx.x;
    if (e < E) {
        int p = atomicAdd(&g_pos[src[e]], 1);
        g_col[p] = dst[e];
    }
}

// ---------------- GEMM (R1 kernel + row-offset for chunking) ------------------
// ht[row] = leaky_relu(in[row] @ W + b); fused s_left/s_right dots.
__global__ __launch_bounds__(256) void k_gemm(
    const float* __restrict__ in,
    const float* __restrict__ W, const float* __restrict__ bias,
    const float* __restrict__ aw,
    float* __restrict__ htout, float* __restrict__ slout, float* __restrict__ srout,
    int r0base, int M)
{
    __shared__ float ws[64 * 128];
    __shared__ float hs[64 * 64];

    int tid = threadIdx.x, warp = tid >> 5, lane = tid & 31;
    int r0 = r0base + blockIdx.x * 64;
    int c4 = lane * 4;

    float4 acc[8];
#pragma unroll
    for (int r = 0; r < 8; r++) acc[r] = make_float4(0.f, 0.f, 0.f, 0.f);

    for (int kc = 0; kc < DD; kc += 64) {
        const float4* wsrc = (const float4*)(W + (size_t)kc * DD);
        float4* wdst = (float4*)ws;
#pragma unroll
        for (int i = 0; i < 8; i++) wdst[tid + i * 256] = wsrc[tid + i * 256];
#pragma unroll
        for (int i = 0; i < 4; i++) {
            int idx = tid + i * 256;
            int row = idx >> 4;
            int c = idx & 15;
            float4 v = make_float4(0.f, 0.f, 0.f, 0.f);
            if (r0 + row < M)
                v = *(const float4*)(in + (size_t)(r0 + row) * DD + kc + c * 4);
            *(float4*)(hs + row * 64 + c * 4) = v;
        }
        __syncthreads();
        int wr = warp * 8;
#pragma unroll 8
        for (int k = 0; k < 64; k++) {
            float4 w4 = *(const float4*)(ws + k * DD + c4);
#pragma unroll
            for (int r = 0; r < 8; r++) {
                float a = hs[(wr + r) * 64 + k];
                acc[r].x += a * w4.x; acc[r].y += a * w4.y;
                acc[r].z += a * w4.z; acc[r].w += a * w4.w;
            }
        }
        __syncthreads();
    }

    float4 bb = *(const float4*)(bias + c4);
    float4 al = *(const float4*)(aw + c4);
    float4 ar = *(const float4*)(aw + DD + c4);
#pragma unroll
    for (int r = 0; r < 8; r++) {
        int row = r0 + warp * 8 + r;
        if (row < M) {
            float4 v = acc[r];
            v.x += bb.x; v.x = v.x > 0.f ? v.x : 0.2f * v.x;
            v.y += bb.y; v.y = v.y > 0.f ? v.y : 0.2f * v.y;
            v.z += bb.z; v.z = v.z > 0.f ? v.z : 0.2f * v.z;
            v.w += bb.w; v.w = v.w > 0.f ? v.w : 0.2f * v.w;
            *(float4*)(htout + (size_t)row * DD + c4) = v;
            float dl = v.x * al.x + v.y * al.y + v.z * al.z + v.w * al.w;
            float dr = v.x * ar.x + v.y * ar.y + v.z * ar.z + v.w * ar.w;
#pragma unroll
            for (int o = 16; o; o >>= 1) {
                dl += __shfl_xor_sync(0xffffffffu, dl, o);
                dr += __shfl_xor_sync(0xffffffffu, dr, o);
            }
            if (lane == 0) { slout[row] = dl; srout[row] = dr; }
        }
    }
}

// ---------------- aggregation (warp per node; row-range for chunking) ---------
__global__ __launch_bounds__(256) void k_agg(
    const float* __restrict__ htin, const float* __restrict__ slin,
    const float* __restrict__ srin, const float* __restrict__ abp,
    float* __restrict__ out, int rbeg, int rend)
{
    int gw = rbeg + ((blockIdx.x * blockDim.x + threadIdx.x) >> 5);
    int lane = threadIdx.x & 31;
    if (gw >= rend) return;

    int base = g_off[gw], end = g_off[gw + 1];
    int c4 = lane * 4;
    float4 acc = make_float4(0.f, 0.f, 0.f, 0.f);

    if (end > base) {
        float ab = *abp;
        float sli = slin[gw];
        float m = -1e30f, s = 0.f;
        for (int k = base + lane; k < end; k += 32) {
            int d = g_col[k];
            float e = sli + srin[d] + ab;
            if (e > m) { s = s * __expf(m - e) + 1.f; m = e; }
            else        { s += __expf(e - m); }
        }
#pragma unroll
        for (int o = 16; o; o >>= 1) {
            float mo = __shfl_xor_sync(0xffffffffu, m, o);
            float so = __shfl_xor_sync(0xffffffffu, s, o);
            float mn = fmaxf(m, mo);
            s = s * __expf(m - mn) + so * __expf(mo - mn);
            m = mn;
        }
        float inv = 1.f / s;
        float csh = sli + ab - m;
        for (int k = base; k < end; k++) {
            int d = g_col[k];
            float w = __expf(csh + srin[d]) * inv;
            float4 hv = *(const float4*)(htin + (size_t)d * DD + c4);
            acc.x += w * hv.x; acc.y += w * hv.y;
            acc.z += w * hv.z; acc.w += w * hv.w;
        }
    }
    acc.x = fmaxf(acc.x, 0.f);
    acc.y = fmaxf(acc.y, 0.f);
    acc.z = fmaxf(acc.z, 0.f);
    acc.w = fmaxf(acc.w, 0.f);
    *(float4*)(out + (size_t)gw * DD + c4) = acc;
}

// ---------------- launch: chunked two-stream pipeline -------------------------
extern "C" void kernel_launch(void* const* d_in, const int* in_sizes, int n_in,
                              void* d_out, int out_size)
{
    const float* x      = (const float*)d_in[0];
    const int*   esrc   = (const int*)d_in[1];
    const int*   edst   = (const int*)d_in[2];
    const float* lin_w  = (const float*)d_in[3];
    const float* lin_b  = (const float*)d_in[4];
    const float* attn_w = (const float*)d_in[5];
    const float* attn_b = (const float*)d_in[6];

    int N = in_sizes[0] / DD;
    int E = in_sizes[1];

    static cudaStream_t s2 = nullptr;
    static cudaEvent_t evStart = nullptr, evG[3], evA[2][NCHUNK];
    if (!s2) {
        cudaStreamCreateWithFlags(&s2, cudaStreamNonBlocking);
        cudaEventCreateWithFlags(&evStart, cudaEventDisableTiming);
        for (int l = 0; l < 3; l++) cudaEventCreateWithFlags(&evG[l], cudaEventDisableTiming);
        for (int b = 0; b < 2; b++)
            for (int c = 0; c < NCHUNK; c++)
                cudaEventCreateWithFlags(&evA[b][c], cudaEventDisableTiming);
    }

    float *h0, *h1, *h2p, *sl0, *sl1, *sr0, *sr1;
    cudaGetSymbolAddress((void**)&h0, g_h);   h1 = h0 + (size_t)NMAX * DD;
    cudaGetSymbolAddress((void**)&h2p, g_h2);
    cudaGetSymbolAddress((void**)&sl0, g_slb); sl1 = sl0 + NMAX;
    cudaGetSymbolAddress((void**)&sr0, g_srb); sr1 = sr0 + NMAX;
    float* hb[2]  = {h0, h1};
    float* slb[2] = {sl0, sl1};
    float* srb[2] = {sr0, sr1};

    int gB = (N + 63) / 64;
    int chunkBlocks = (gB + NCHUNK - 1) / NCHUNK;
    int chunkRows = chunkBlocks * 64;

    // fork: CSR build on s2 concurrent with layer-0 GEMM on stream 0
    cudaEventRecord(evStart, 0);
    cudaStreamWaitEvent(s2, evStart, 0);
    k_zero<<<(N + 255) / 256, 256, 0, s2>>>(N);
    k_count<<<(E + 255) / 256, 256, 0, s2>>>(esrc, E);
    k_scan<<<1, 1024, 0, s2>>>(N, E);
    k_scatter<<<(E + 255) / 256, 256, 0, s2>>>(esrc, edst, E);

    // layer-0 GEMM (whole) on stream 0
    k_gemm<<<gB, 256>>>(x, lin_w, lin_b, attn_w, hb[0], slb[0], srb[0], 0, N);
    cudaEventRecord(evG[0], 0);

    // boundaries l=0,1: agg(l) chunks on s2, gemm(l+1) chunks on stream 0
    for (int l = 0; l < 2; l++) {
        int bin = l & 1, bout = (l + 1) & 1;
        cudaStreamWaitEvent(s2, evG[l], 0);
        for (int c = 0; c < NCHUNK; c++) {
            int rbeg = c * chunkRows;
            int rend = rbeg + chunkRows; if (rend > N) rend = N;
            if (rbeg >= rend) { cudaEventRecord(evA[l][c], s2); continue; }
            int aGrid = (rend - rbeg + 7) / 8;
            k_agg<<<aGrid, 256, 0, s2>>>(hb[bin], slb[bin], srb[bin],
                                         attn_b + l, h2p, rbeg, rend);
            cudaEventRecord(evA[l][c], s2);
        }
        for (int c = 0; c < NCHUNK; c++) {
            int rbeg = c * chunkRows;
            int rend = rbeg + chunkRows; if (rend > N) rend = N;
            cudaStreamWaitEvent(0, evA[l][c], 0);
            if (rbeg >= rend) continue;
            int gGrid = (rend - rbeg + 63) / 64;
            k_gemm<<<gGrid, 256>>>(h2p,
                                   lin_w + (size_t)(l + 1) * DD * DD,
                                   lin_b + (size_t)(l + 1) * DD,
                                   attn_w + (size_t)(l + 1) * 2 * DD,
                                   hb[bout], slb[bout], srb[bout], rbeg, N);
        }
        cudaEventRecord(evG[l + 1], 0);
    }

    // final aggregation (layer 2) -> d_out, on stream 0 (s2 already joined via evA[1][*])
    int aB = (N + 7) / 8;
    k_agg<<<aB, 256>>>(hb[0], slb[0], srb[0], attn_b + 2, (float*)d_out, 0, N);
}

// round 13
// speedup vs baseline: 1.6234x; 1.6234x over previous
#include <cuda_runtime.h>
#include <cstdint>

#define DD 128
#define NMAX 50176
#define EMAX 800256

// ---------------- scratch (__device__ globals; no allocation) ----------------
__device__ float g_ht[(size_t)NMAX * DD];   // post-linear h
__device__ float g_h2[(size_t)NMAX * DD];   // aggregated h (next gemm input)
__device__ float g_sl[NMAX], g_sr[NMAX];
__device__ int   g_deg[NMAX];
__device__ int   g_off[NMAX + 1];
__device__ int   g_pos[NMAX];
__device__ int   g_col[EMAX];

// ---------------- CSR build ----------------
__global__ void k_zero(int N) {
    int i = blockIdx.x * blockDim.x + threadIdx.x;
    if (i < N) g_deg[i] = 0;
}
__global__ void k_count(const int* __restrict__ src, int E) {
    int e = blockIdx.x * blockDim.x + threadIdx.x;
    if (e < E) atomicAdd(&g_deg[src[e]], 1);
}
__global__ __launch_bounds__(1024) void k_scan(int N, int E) {
    __shared__ int sh[1024];
    int tid = threadIdx.x;
    int per = (N + 1023) >> 10;
    int s = tid * per;
    int e = s + per; if (e > N) e = N;
    int sum = 0;
    for (int i = s; i < e; i++) sum += g_deg[i];
    sh[tid] = sum;
    __syncthreads();
    for (int o = 1; o < 1024; o <<= 1) {
        int t = (tid >= o) ? sh[tid - o] : 0;
        __syncthreads();
        sh[tid] += t;
        __syncthreads();
    }
    int run = sh[tid] - sum;
    for (int i = s; i < e; i++) { g_off[i] = run; g_pos[i] = run; run += g_deg[i]; }
    if (tid == 1023) g_off[N] = E;
}
__global__ void k_scatter(const int* __restrict__ src, const int* __restrict__ dst, int E) {
    int e = blockIdx.x * blockDim.x + threadIdx.x;
    if (e < E) {
        int p = atomicAdd(&g_pos[src[e]], 1);
        g_col[p] = dst[e];
    }
}

// ---------------- GEMM (R1 kernel): ht = leaky_relu(in @ W + b) + fused dots --
__global__ __launch_bounds__(256) void k_gemm(
    const float* __restrict__ in,
    const float* __restrict__ W, const float* __restrict__ bias,
    const float* __restrict__ aw, int M)
{
    __shared__ float ws[64 * 128];   // 32 KB  W chunk [64k x 128n]
    __shared__ float hs[64 * 64];    // 16 KB  h tile  [64rows x 64k]

    int tid = threadIdx.x, warp = tid >> 5, lane = tid & 31;
    int r0 = blockIdx.x * 64;
    int c4 = lane * 4;

    float4 acc[8];
#pragma unroll
    for (int r = 0; r < 8; r++) acc[r] = make_float4(0.f, 0.f, 0.f, 0.f);

    for (int kc = 0; kc < DD; kc += 64) {
        const float4* wsrc = (const float4*)(W + (size_t)kc * DD);
        float4* wdst = (float4*)ws;
#pragma unroll
        for (int i = 0; i < 8; i++) wdst[tid + i * 256] = wsrc[tid + i * 256];
#pragma unroll
        for (int i = 0; i < 4; i++) {
            int idx = tid + i * 256;
            int row = idx >> 4;
            int c = idx & 15;
            float4 v = make_float4(0.f, 0.f, 0.f, 0.f);
            if (r0 + row < M)
                v = *(const float4*)(in + (size_t)(r0 + row) * DD + kc + c * 4);
            *(float4*)(hs + row * 64 + c * 4) = v;
        }
        __syncthreads();
        int wr = warp * 8;
#pragma unroll 8
        for (int k = 0; k < 64; k++) {
            float4 w4 = *(const float4*)(ws + k * DD + c4);
#pragma unroll
            for (int r = 0; r < 8; r++) {
                float a = hs[(wr + r) * 64 + k];
                acc[r].x += a * w4.x; acc[r].y += a * w4.y;
                acc[r].z += a * w4.z; acc[r].w += a * w4.w;
            }
        }
        __syncthreads();
    }

    float4 bb = *(const float4*)(bias + c4);
    float4 al = *(const float4*)(aw + c4);
    float4 ar = *(const float4*)(aw + DD + c4);
#pragma unroll
    for (int r = 0; r < 8; r++) {
        int row = r0 + warp * 8 + r;
        if (row < M) {
            float4 v = acc[r];
            v.x += bb.x; v.x = v.x > 0.f ? v.x : 0.2f * v.x;
            v.y += bb.y; v.y = v.y > 0.f ? v.y : 0.2f * v.y;
            v.z += bb.z; v.z = v.z > 0.f ? v.z : 0.2f * v.z;
            v.w += bb.w; v.w = v.w > 0.f ? v.w : 0.2f * v.w;
            *(float4*)(g_ht + (size_t)row * DD + c4) = v;
            float dl = v.x * al.x + v.y * al.y + v.z * al.z + v.w * al.w;
            float dr = v.x * ar.x + v.y * ar.y + v.z * ar.z + v.w * ar.w;
#pragma unroll
            for (int o = 16; o; o >>= 1) {
                dl += __shfl_xor_sync(0xffffffffu, dl, o);
                dr += __shfl_xor_sync(0xffffffffu, dr, o);
            }
            if (lane == 0) { g_sl[row] = dl; g_sr[row] = dr; }
        }
    }
}

// ---------------- aggregation (R1 kernel, warp per node) ----------------------
__global__ __launch_bounds__(256) void k_agg(
    float* __restrict__ out, const float* __restrict__ abp, int N)
{
    const float* ht = g_ht;
    int gw = (blockIdx.x * blockDim.x + threadIdx.x) >> 5;
    int lane = threadIdx.x & 31;
    if (gw >= N) return;

    int base = g_off[gw], end = g_off[gw + 1];
    int c4 = lane * 4;
    float4 acc = make_float4(0.f, 0.f, 0.f, 0.f);

    if (end > base) {
        float ab = *abp;
        float sli = g_sl[gw];
        float m = -1e30f, s = 0.f;
        for (int k = base + lane; k < end; k += 32) {
            int d = g_col[k];
            float e = sli + g_sr[d] + ab;
            if (e > m) { s = s * __expf(m - e) + 1.f; m = e; }
            else        { s += __expf(e - m); }
        }
#pragma unroll
        for (int o = 16; o; o >>= 1) {
            float mo = __shfl_xor_sync(0xffffffffu, m, o);
            float so = __shfl_xor_sync(0xffffffffu, s, o);
            float mn = fmaxf(m, mo);
            s = s * __expf(m - mn) + so * __expf(mo - mn);
            m = mn;
        }
        float inv = 1.f / s;
        float csh = sli + ab - m;
        for (int k = base; k < end; k++) {
            int d = g_col[k];
            float w = __expf(csh + g_sr[d]) * inv;
            float4 hv = *(const float4*)(ht + (size_t)d * DD + c4);
            acc.x += w * hv.x; acc.y += w * hv.y;
            acc.z += w * hv.z; acc.w += w * hv.w;
        }
    }
    acc.x = fmaxf(acc.x, 0.f);
    acc.y = fmaxf(acc.y, 0.f);
    acc.z = fmaxf(acc.z, 0.f);
    acc.w = fmaxf(acc.w, 0.f);
    *(float4*)(out + (size_t)gw * DD + c4) = acc;
}

// ---------------- launch ----------------
extern "C" void kernel_launch(void* const* d_in, const int* in_sizes, int n_in,
                              void* d_out, int out_size)
{
    const float* x      = (const float*)d_in[0];
    const int*   esrc   = (const int*)d_in[1];
    const int*   edst   = (const int*)d_in[2];
    const float* lin_w  = (const float*)d_in[3];
    const float* lin_b  = (const float*)d_in[4];
    const float* attn_w = (const float*)d_in[5];
    const float* attn_b = (const float*)d_in[6];

    int N = in_sizes[0] / DD;
    int E = in_sizes[1];

    static cudaStream_t s2 = nullptr;
    static cudaEvent_t evStart = nullptr, evCsr = nullptr;
    if (!s2) {
        cudaStreamCreateWithFlags(&s2, cudaStreamNonBlocking);
        cudaEventCreateWithFlags(&evStart, cudaEventDisableTiming);
        cudaEventCreateWithFlags(&evCsr, cudaEventDisableTiming);
    }

    float* h2p;
    cudaGetSymbolAddress((void**)&h2p, g_h2);

    int gB = (N + 63) / 64;
    int aB = (N + 7) / 8;

    // fork: CSR build on s2 concurrent with layer-0 GEMM on stream 0
    cudaEventRecord(evStart, 0);
    cudaStreamWaitEvent(s2, evStart, 0);
    k_zero<<<(N + 255) / 256, 256, 0, s2>>>(N);
    k_count<<<(E + 255) / 256, 256, 0, s2>>>(esrc, E);
    k_scan<<<1, 1024, 0, s2>>>(N, E);
    k_scatter<<<(E + 255) / 256, 256, 0, s2>>>(esrc, edst, E);
    cudaEventRecord(evCsr, s2);

    // layer-0 GEMM on stream 0 (overlaps CSR build)
    k_gemm<<<gB, 256>>>(x, lin_w, lin_b, attn_w, N);

    cudaStreamWaitEvent(0, evCsr, 0);   // join: aggregation needs CSR

    // layer 0 boundary
    k_agg<<<aB, 256>>>(h2p, attn_b + 0, N);
    k_gemm<<<gB, 256>>>(h2p, lin_w + (size_t)1 * DD * DD, lin_b + DD,
                        attn_w + (size_t)1 * 2 * DD, N);
    // layer 1 boundary
    k_agg<<<aB, 256>>>(h2p, attn_b + 1, N);
    k_gemm<<<gB, 256>>>(h2p, lin_w + (size_t)2 * DD * DD, lin_b + 2 * DD,
                        attn_w + (size_t)2 * 2 * DD, N);
    // final aggregation -> d_out
    k_agg<<<aB, 256>>>((float*)d_out, attn_b + 2, N);
}

// round 14
// speedup vs baseline: 1.6289x; 1.0034x over previous
#include <cuda_runtime.h>
#include <cstdint>

#define DD 128
#define NMAX 50176
#define EMAX 800256

// ---------------- scratch (__device__ globals; no allocation) ----------------
__device__ float g_ht[(size_t)NMAX * DD];   // post-linear h
__device__ float g_h2[(size_t)NMAX * DD];   // aggregated h (next gemm input)
__device__ float g_sl[NMAX], g_sr[NMAX];
__device__ float g_ew[EMAX];                // cached edge scores e = sl[i]+sr[j]+b
__device__ int   g_deg[NMAX];
__device__ int   g_off[NMAX + 1];
__device__ int   g_pos[NMAX];
__device__ int   g_col[EMAX];

// ---------------- CSR build ----------------
__global__ void k_count(const int* __restrict__ src, int E) {
    int i = blockIdx.x * blockDim.x + threadIdx.x;
    int e4 = E >> 2;
    if (i < e4) {
        int4 s = ((const int4*)src)[i];
        atomicAdd(&g_deg[s.x], 1);
        atomicAdd(&g_deg[s.y], 1);
        atomicAdd(&g_deg[s.z], 1);
        atomicAdd(&g_deg[s.w], 1);
    } else {
        int k = e4 * 4 + (i - e4);
        if (k < E) atomicAdd(&g_deg[src[k]], 1);
    }
}
__global__ __launch_bounds__(1024) void k_scan(int N, int E) {
    __shared__ int sh[1024];
    int tid = threadIdx.x;
    int per = (N + 1023) >> 10;
    int s = tid * per;
    int e = s + per; if (e > N) e = N;
    int sum = 0;
    for (int i = s; i < e; i++) sum += g_deg[i];
    sh[tid] = sum;
    __syncthreads();
    for (int o = 1; o < 1024; o <<= 1) {
        int t = (tid >= o) ? sh[tid - o] : 0;
        __syncthreads();
        sh[tid] += t;
        __syncthreads();
    }
    int run = sh[tid] - sum;
    for (int i = s; i < e; i++) { g_off[i] = run; g_pos[i] = run; run += g_deg[i]; }
    if (tid == 1023) g_off[N] = E;
}
__global__ void k_scatter(const int* __restrict__ src, const int* __restrict__ dst, int E) {
    int i = blockIdx.x * blockDim.x + threadIdx.x;
    int e4 = E >> 2;
    if (i < e4) {
        int4 s = ((const int4*)src)[i];
        int4 d = ((const int4*)dst)[i];
        g_col[atomicAdd(&g_pos[s.x], 1)] = d.x;
        g_col[atomicAdd(&g_pos[s.y], 1)] = d.y;
        g_col[atomicAdd(&g_pos[s.z], 1)] = d.z;
        g_col[atomicAdd(&g_pos[s.w], 1)] = d.w;
    } else {
        int k = e4 * 4 + (i - e4);
        if (k < E) g_col[atomicAdd(&g_pos[src[k]], 1)] = dst[k];
    }
}

// ---------------- GEMM (R1 kernel): ht = leaky_relu(in @ W + b) + fused dots --
__global__ __launch_bounds__(256) void k_gemm(
    const float* __restrict__ in,
    const float* __restrict__ W, const float* __restrict__ bias,
    const float* __restrict__ aw, int M)
{
    __shared__ float ws[64 * 128];   // 32 KB  W chunk [64k x 128n]
    __shared__ float hs[64 * 64];    // 16 KB  h tile  [64rows x 64k]

    int tid = threadIdx.x, warp = tid >> 5, lane = tid & 31;
    int r0 = blockIdx.x * 64;
    int c4 = lane * 4;

    float4 acc[8];
#pragma unroll
    for (int r = 0; r < 8; r++) acc[r] = make_float4(0.f, 0.f, 0.f, 0.f);

    for (int kc = 0; kc < DD; kc += 64) {
        const float4* wsrc = (const float4*)(W + (size_t)kc * DD);
        float4* wdst = (float4*)ws;
#pragma unroll
        for (int i = 0; i < 8; i++) wdst[tid + i * 256] = wsrc[tid + i * 256];
#pragma unroll
        for (int i = 0; i < 4; i++) {
            int idx = tid + i * 256;
            int row = idx >> 4;
            int c = idx & 15;
            float4 v = make_float4(0.f, 0.f, 0.f, 0.f);
            if (r0 + row < M)
                v = *(const float4*)(in + (size_t)(r0 + row) * DD + kc + c * 4);
            *(float4*)(hs + row * 64 + c * 4) = v;
        }
        __syncthreads();
        int wr = warp * 8;
#pragma unroll 8
        for (int k = 0; k < 64; k++) {
            float4 w4 = *(const float4*)(ws + k * DD + c4);
#pragma unroll
            for (int r = 0; r < 8; r++) {
                float a = hs[(wr + r) * 64 + k];
                acc[r].x += a * w4.x; acc[r].y += a * w4.y;
                acc[r].z += a * w4.z; acc[r].w += a * w4.w;
            }
        }
        __syncthreads();
    }

    float4 bb = *(const float4*)(bias + c4);
    float4 al = *(const float4*)(aw + c4);
    float4 ar = *(const float4*)(aw + DD + c4);
#pragma unroll
    for (int r = 0; r < 8; r++) {
        int row = r0 + warp * 8 + r;
        if (row < M) {
            float4 v = acc[r];
            v.x += bb.x; v.x = v.x > 0.f ? v.x : 0.2f * v.x;
            v.y += bb.y; v.y = v.y > 0.f ? v.y : 0.2f * v.y;
            v.z += bb.z; v.z = v.z > 0.f ? v.z : 0.2f * v.z;
            v.w += bb.w; v.w = v.w > 0.f ? v.w : 0.2f * v.w;
            *(float4*)(g_ht + (size_t)row * DD + c4) = v;
            float dl = v.x * al.x + v.y * al.y + v.z * al.z + v.w * al.w;
            float dr = v.x * ar.x + v.y * ar.y + v.z * ar.z + v.w * ar.w;
#pragma unroll
            for (int o = 16; o; o >>= 1) {
                dl += __shfl_xor_sync(0xffffffffu, dl, o);
                dr += __shfl_xor_sync(0xffffffffu, dr, o);
            }
            if (lane == 0) { g_sl[row] = dl; g_sr[row] = dr; }
        }
    }
}

// ---------------- aggregation (warp per node; e cached pass1 -> pass2) --------
__global__ __launch_bounds__(256) void k_agg(
    float* __restrict__ out, const float* __restrict__ abp, int N)
{
    const float* ht = g_ht;
    int gw = (blockIdx.x * blockDim.x + threadIdx.x) >> 5;
    int lane = threadIdx.x & 31;
    if (gw >= N) return;

    int base = g_off[gw], end = g_off[gw + 1];
    int c4 = lane * 4;
    float4 acc = make_float4(0.f, 0.f, 0.f, 0.f);

    if (end > base) {
        float ab = *abp;
        float sli = g_sl[gw];
        // pass 1: online softmax stats; cache e (coalesced 128B warp writes)
        float m = -1e30f, s = 0.f;
        for (int k = base + lane; k < end; k += 32) {
            int d = g_col[k];
            float e = sli + g_sr[d] + ab;
            g_ew[k] = e;
            if (e > m) { s = s * __expf(m - e) + 1.f; m = e; }
            else        { s += __expf(e - m); }
        }
#pragma unroll
        for (int o = 16; o; o >>= 1) {
            float mo = __shfl_xor_sync(0xffffffffu, m, o);
            float so = __shfl_xor_sync(0xffffffffu, s, o);
            float mn = fmaxf(m, mo);
            s = s * __expf(m - mn) + so * __expf(mo - mn);
            m = mn;
        }
        float inv = 1.f / s;
        // pass 2: per-edge weight from cached e (broadcast read), 512B row read
        for (int k = base; k < end; k++) {
            int d = g_col[k];
            float w = __expf(g_ew[k] - m) * inv;
            float4 hv = *(const float4*)(ht + (size_t)d * DD + c4);
            acc.x += w * hv.x; acc.y += w * hv.y;
            acc.z += w * hv.z; acc.w += w * hv.w;
        }
    }
    acc.x = fmaxf(acc.x, 0.f);
    acc.y = fmaxf(acc.y, 0.f);
    acc.z = fmaxf(acc.z, 0.f);
    acc.w = fmaxf(acc.w, 0.f);
    *(float4*)(out + (size_t)gw * DD + c4) = acc;
}

// ---------------- launch: single stream, R1 structure -------------------------
extern "C" void kernel_launch(void* const* d_in, const int* in_sizes, int n_in,
                              void* d_out, int out_size)
{
    const float* x      = (const float*)d_in[0];
    const int*   esrc   = (const int*)d_in[1];
    const int*   edst   = (const int*)d_in[2];
    const float* lin_w  = (const float*)d_in[3];
    const float* lin_b  = (const float*)d_in[4];
    const float* attn_w = (const float*)d_in[5];
    const float* attn_b = (const float*)d_in[6];

    int N = in_sizes[0] / DD;
    int E = in_sizes[1];

    void* degp = nullptr;
    cudaGetSymbolAddress(&degp, g_deg);
    float* h2p = nullptr;
    cudaGetSymbolAddress((void**)&h2p, g_h2);

    int gB = (N + 63) / 64;
    int aB = (N + 7) / 8;
    int cT = (E >> 2) + (E & 3);        // int4 threads + remainder

    // CSR build (single stream; fork was measured harmful)
    cudaMemsetAsync(degp, 0, (size_t)N * sizeof(int), 0);
    k_count<<<(cT + 255) / 256, 256>>>(esrc, E);
    k_scan<<<1, 1024>>>(N, E);
    k_scatter<<<(cT + 255) / 256, 256>>>(esrc, edst, E);

    // layer 0
    k_gemm<<<gB, 256>>>(x, lin_w, lin_b, attn_w, N);
    k_agg<<<aB, 256>>>(h2p, attn_b + 0, N);
    // layer 1
    k_gemm<<<gB, 256>>>(h2p, lin_w + (size_t)1 * DD * DD, lin_b + DD,
                        attn_w + (size_t)1 * 2 * DD, N);
    k_agg<<<aB, 256>>>(h2p, attn_b + 1, N);
    // layer 2
    k_gemm<<<gB, 256>>>(h2p, lin_w + (size_t)2 * DD * DD, lin_b + 2 * DD,
                        attn_w + (size_t)2 * 2 * DD, N);
    k_agg<<<aB, 256>>>((float*)d_out, attn_b + 2, N);
}